// round 1
// baseline (speedup 1.0000x reference)
#include <cuda_runtime.h>
#include <math.h>

#define NUM_CLASSES 1000
#define FEAT_DIM    256
#define NROWS       262144
#define ALPHA       0.5f

// Scratch (no device allocation allowed -> __device__ globals)
__device__ float g_sums[NUM_CLASSES * FEAT_DIM];   // per-class feature sums
__device__ float g_counts[NUM_CLASSES];            // per-class counts
__device__ float g_loss;                           // sum of distances
__device__ int   g_is64;                           // 1 if labels are int64

// ---------------------------------------------------------------------------
// Kernel 0: zero scratch + detect label dtype (int64 vs int32)
// ---------------------------------------------------------------------------
__global__ void cl_zero_kernel(const void* __restrict__ labels_raw) {
    int i = blockIdx.x * blockDim.x + threadIdx.x;
    if (i < NUM_CLASSES * FEAT_DIM) g_sums[i] = 0.0f;
    if (i < NUM_CLASSES)            g_counts[i] = 0.0f;
    if (i == 0) {
        g_loss = 0.0f;
        // If data is int64 (little-endian values < 1000), every odd 32-bit
        // word is 0. If data is int32 labels, odd words are labels themselves
        // (zero w.p. 1/1000 each). Check 64 odd words: false positive ~0.
        const int* w = (const int*)labels_raw;
        int all_zero = 1;
        #pragma unroll 8
        for (int k = 0; k < 64; k++) {
            if (w[2 * k + 1] != 0) { all_zero = 0; break; }
        }
        g_is64 = all_zero;
    }
}

// Vectorized reduction-add to global (sm_90+): 4 floats in one op.
__device__ __forceinline__ void red_add_v4(float* addr, float4 v) {
    asm volatile("red.global.add.v4.f32 [%0], {%1, %2, %3, %4};"
                 :: "l"(addr), "f"(v.x), "f"(v.y), "f"(v.z), "f"(v.w)
                 : "memory");
}

// ---------------------------------------------------------------------------
// Kernel 1: fused loss + segment-sum scatter. One warp per row (grid-stride).
// Row = 256 floats: lane l handles dims [4l,4l+4) and [128+4l, 128+4l+4).
// ---------------------------------------------------------------------------
__global__ void __launch_bounds__(256)
cl_main_kernel(const float* __restrict__ x,
               const void*  __restrict__ labels_raw,
               const float* __restrict__ centers) {
    __shared__ float s_loss;
    if (threadIdx.x == 0) s_loss = 0.0f;
    __syncthreads();

    const int is64 = g_is64;
    const int lane = threadIdx.x & 31;
    const int warp_in_block = threadIdx.x >> 5;
    const int warps_per_block = blockDim.x >> 5;
    const int gwarp = blockIdx.x * warps_per_block + warp_in_block;
    const int nwarps = gridDim.x * warps_per_block;

    const long long* __restrict__ lab64 = (const long long*)labels_raw;
    const int*       __restrict__ lab32 = (const int*)labels_raw;

    float loss_acc = 0.0f;  // meaningful on lane 0 only

    for (int row = gwarp; row < NROWS; row += nwarps) {
        const int lbl = is64 ? (int)lab64[row] : lab32[row];

        const float4* __restrict__ xr = (const float4*)(x + (size_t)row * FEAT_DIM);
        const float4* __restrict__ cr = (const float4*)(centers + (size_t)lbl * FEAT_DIM);

        float4 xa = xr[lane];
        float4 xb = xr[lane + 32];
        float4 ca = cr[lane];
        float4 cb = cr[lane + 32];

        float d0 = xa.x - ca.x, d1 = xa.y - ca.y, d2 = xa.z - ca.z, d3 = xa.w - ca.w;
        float e0 = xb.x - cb.x, e1 = xb.y - cb.y, e2 = xb.z - cb.z, e3 = xb.w - cb.w;
        float ss = d0 * d0 + d1 * d1 + d2 * d2 + d3 * d3
                 + e0 * e0 + e1 * e1 + e2 * e2 + e3 * e3;

        // warp reduction of squared distance
        #pragma unroll
        for (int o = 16; o > 0; o >>= 1)
            ss += __shfl_xor_sync(0xFFFFFFFFu, ss, o);

        if (lane == 0) loss_acc += sqrtf(ss);

        // scatter row into per-class sums (vectorized reduction, no return)
        float* base = g_sums + (size_t)lbl * FEAT_DIM;
        red_add_v4(base + lane * 4, xa);
        red_add_v4(base + 128 + lane * 4, xb);
        if (lane == 0) atomicAdd(&g_counts[lbl], 1.0f);
    }

    if (lane == 0) atomicAdd(&s_loss, loss_acc);
    __syncthreads();
    if (threadIdx.x == 0) atomicAdd(&g_loss, s_loss);
}

// ---------------------------------------------------------------------------
// Kernel 2: finalize. out[0] = loss, out[1..256000] = new_centers.
// ---------------------------------------------------------------------------
__global__ void cl_finalize_kernel(const float* __restrict__ centers,
                                   float* __restrict__ out) {
    int i = blockIdx.x * blockDim.x + threadIdx.x;
    if (i == 0) {
        out[0] = g_loss * (0.5f / (float)NROWS);
    }
    if (i < NUM_CLASSES * FEAT_DIM) {
        int c = i / FEAT_DIM;
        float cnt = g_counts[c];
        float cen = centers[i];
        float res = cen;
        if (cnt > 0.0f) {
            float mean = g_sums[i] / cnt;        // cnt >= 1 here
            res = cen + ALPHA * (mean - cen);
        }
        out[1 + i] = res;
    }
}

// ---------------------------------------------------------------------------
extern "C" void kernel_launch(void* const* d_in, const int* in_sizes, int n_in,
                              void* d_out, int out_size) {
    const float* x       = (const float*)d_in[0];
    const void*  labels  = d_in[1];
    const float* centers = (const float*)d_in[2];
    float*       out     = (float*)d_out;

    (void)in_sizes; (void)n_in; (void)out_size;

    // Zero scratch + dtype detect
    {
        int total = NUM_CLASSES * FEAT_DIM;
        cl_zero_kernel<<<(total + 255) / 256, 256>>>(labels);
    }
    // Fused loss + segment sums: 8 warps/block, ~8 blocks/SM resident
    cl_main_kernel<<<1184, 256>>>(x, labels, centers);
    // Finalize
    {
        int total = NUM_CLASSES * FEAT_DIM;
        cl_finalize_kernel<<<(total + 255) / 256, 256>>>(centers, out);
    }
}